// round 6
// baseline (speedup 1.0000x reference)
#include <cuda_runtime.h>
#include <cuda_bf16.h>
#include <math.h>

#define BDIM 8
#define SDIM 1024
#define HDIM 128
#define BS   (BDIM*SDIM)
#define PDIM 129
#define PW   132
#define INV_SCALE 0.08838834764831845f   // 1/sqrt(128)
#define LN_EPS 1e-5f

// ---- scratch (device globals; no runtime allocation allowed) ----
__device__ float g_q[BS*HDIM];
__device__ float g_k[BS*HDIM];
__device__ float g_v[BS*HDIM];
__device__ float g_w[BS*PW];
__device__ float g_ctx[BS*HDIM];
__device__ float g_attn[BDIM*SDIM*SDIM];

// ============================================================================
// K1: q/k/v = x @ W + b   (grid.y selects which of the three)
// M=8192, N=128, K=128. Tile 64x128, K-chunk 32.
// ============================================================================
__global__ __launch_bounds__(256) void k_qkv(
    const float* __restrict__ x,
    const float* __restrict__ Wq, const float* __restrict__ bq,
    const float* __restrict__ Wk, const float* __restrict__ bk,
    const float* __restrict__ Wv, const float* __restrict__ bv)
{
    __shared__ float xs[64][33];
    __shared__ float Ws[32][128];
    int which = blockIdx.y;
    const float* Wg = (which==0) ? Wq : (which==1 ? Wk : Wv);
    const float* bg = (which==0) ? bq : (which==1 ? bk : bv);
    float* outg     = (which==0) ? g_q : (which==1 ? g_k : g_v);

    int r0 = blockIdx.x * 64;
    int t  = threadIdx.x;
    int tx = t & 31, ty = t >> 5;

    float acc[8][4];
    #pragma unroll
    for (int r = 0; r < 8; r++)
        #pragma unroll
        for (int c = 0; c < 4; c++) acc[r][c] = 0.f;

    for (int kc = 0; kc < HDIM; kc += 32) {
        #pragma unroll
        for (int e = 0; e < 8; e++) {
            int f = t + e*256; int row = f >> 5, col = f & 31;
            xs[row][col] = x[(r0+row)*HDIM + kc + col];
        }
        #pragma unroll
        for (int e = 0; e < 16; e++) {
            int f = t + e*256; int kr = f >> 7, col = f & 127;
            Ws[kr][col] = Wg[(kc+kr)*HDIM + col];
        }
        __syncthreads();
        #pragma unroll
        for (int kk = 0; kk < 32; kk++) {
            float4 b4 = *(const float4*)&Ws[kk][tx*4];
            #pragma unroll
            for (int r = 0; r < 8; r++) {
                float a = xs[ty*8+r][kk];
                acc[r][0] += a*b4.x; acc[r][1] += a*b4.y;
                acc[r][2] += a*b4.z; acc[r][3] += a*b4.w;
            }
        }
        __syncthreads();
    }
    float4 bias = *(const float4*)&bg[tx*4];
    #pragma unroll
    for (int r = 0; r < 8; r++) {
        float4 o = make_float4(acc[r][0]+bias.x, acc[r][1]+bias.y,
                               acc[r][2]+bias.z, acc[r][3]+bias.w);
        *(float4*)&outg[(r0 + ty*8 + r)*HDIM + tx*4] = o;
    }
}

// ============================================================================
// K2: per 16-row tile: scores = q@k^T/scale + qrel(clip(j-i)), softmax,
//     write attn, extract w[b,i,p] (incl. prefix/suffix edge sums).
// Dynamic smem: q(16x128) + qrel(16x132) + k(64x132) + scores(16x1024)
// ============================================================================
#define SC_SMEM_FLOATS (16*128 + 16*PW + 64*PW + 16*1024)
#define SC_SMEM_BYTES  (SC_SMEM_FLOATS*4)

__global__ __launch_bounds__(256) void k_scores(
    const float* __restrict__ rel_k, float* __restrict__ attn)
{
    extern __shared__ float sm[];
    float* q_s  = sm;                        // 16*128
    float* qr_s = q_s  + 16*128;             // 16*PW
    float* k_s  = qr_s + 16*PW;              // 64*PW
    float* sc   = k_s  + 64*PW;              // 16*1024

    int b  = blockIdx.y;
    int i0 = blockIdx.x * 16;
    int t  = threadIdx.x;

    // load 16 q rows
    #pragma unroll
    for (int e = 0; e < 8; e++) {
        int f = t + e*256; int row = f >> 7, col = f & 127;
        q_s[row*128 + col] = g_q[(b*SDIM + i0 + row)*HDIM + col];
    }
    __syncthreads();

    // qrel[row][p] = q_row . rel_k[p]
    for (int idx = t; idx < 16*PDIM; idx += 256) {
        int row = idx / PDIM, p = idx - row*PDIM;
        const float4* qp = (const float4*)&q_s[row*128];
        const float4* rp = (const float4*)&rel_k[p*HDIM];
        float acc = 0.f;
        #pragma unroll
        for (int kk = 0; kk < 32; kk++) {
            float4 a = qp[kk], c = rp[kk];
            acc += a.x*c.x + a.y*c.y + a.z*c.z + a.w*c.w;
        }
        qr_s[row*PW + p] = acc;
    }
    __syncthreads();

    int tj = t & 63, tg = t >> 6;
    for (int jc = 0; jc < SDIM; jc += 64) {
        #pragma unroll
        for (int e = 0; e < 32; e++) {
            int f = t + e*256; int row = f >> 7, col = f & 127;
            k_s[row*PW + col] = g_k[(b*SDIM + jc + row)*HDIM + col];
        }
        __syncthreads();
        float acc[4] = {0.f, 0.f, 0.f, 0.f};
        #pragma unroll
        for (int kk = 0; kk < 128; kk += 4) {
            float4 kb = *(const float4*)&k_s[tj*PW + kk];
            #pragma unroll
            for (int rr = 0; rr < 4; rr++) {
                float4 qa = *(const float4*)&q_s[(tg*4+rr)*128 + kk];
                acc[rr] += qa.x*kb.x + qa.y*kb.y + qa.z*kb.z + qa.w*kb.w;
            }
        }
        int j = jc + tj;
        #pragma unroll
        for (int rr = 0; rr < 4; rr++) {
            int ir = tg*4 + rr;
            int i  = i0 + ir;
            int d  = j - i;
            d = d < -64 ? -64 : (d > 64 ? 64 : d);
            sc[ir*1024 + j] = acc[rr]*INV_SCALE + qr_s[ir*PW + d + 64];
        }
        __syncthreads();
    }

    // softmax per row; also extract w (edge sums + diagonals)
    int lane = t & 31, wz = t >> 5;
    #pragma unroll
    for (int rr = 0; rr < 2; rr++) {
        int ir = wz*2 + rr;
        int i  = i0 + ir;
        float* srow = &sc[ir*1024];
        float m = -1e30f;
        for (int jj = lane; jj < SDIM; jj += 32) m = fmaxf(m, srow[jj]);
        #pragma unroll
        for (int o = 16; o > 0; o >>= 1) m = fmaxf(m, __shfl_xor_sync(0xffffffffu, m, o));
        float sum = 0.f, low = 0.f, high = 0.f;
        for (int jj = lane; jj < SDIM; jj += 32) {
            float e = __expf(srow[jj] - m);
            srow[jj] = e;
            sum += e;
            if (jj <= i - 64) low  += e;
            if (jj >= i + 64) high += e;
        }
        #pragma unroll
        for (int o = 16; o > 0; o >>= 1) {
            sum  += __shfl_xor_sync(0xffffffffu, sum,  o);
            low  += __shfl_xor_sync(0xffffffffu, low,  o);
            high += __shfl_xor_sync(0xffffffffu, high, o);
        }
        float inv = 1.f / sum;
        float* arow = &attn[(b*SDIM + i)*SDIM];
        for (int jj = lane; jj < SDIM; jj += 32) arow[jj] = srow[jj]*inv;
        for (int p = lane; p < PDIM; p += 32) {
            float wv;
            if (p == 0)        wv = low*inv;
            else if (p == 128) wv = high*inv;
            else {
                int j2 = i + p - 64;
                wv = (j2 >= 0 && j2 < SDIM) ? srow[j2]*inv : 0.f;
            }
            g_w[(b*SDIM + i)*PW + p] = wv;
        }
    }
}

// ============================================================================
// K3: ctx = attn @ v + w @ rel_v.  Tile 64x128, K-chunks of 32.
// ============================================================================
__global__ __launch_bounds__(256) void k_ctx(
    const float* __restrict__ attn, const float* __restrict__ rel_v)
{
    __shared__ float a_s[64][33];
    __shared__ float v_s[32][128];
    int b  = blockIdx.y;
    int i0 = blockIdx.x * 64;
    int t  = threadIdx.x;
    int tx = t & 31, ty = t >> 5;

    float acc[8][4];
    #pragma unroll
    for (int r = 0; r < 8; r++)
        #pragma unroll
        for (int c = 0; c < 4; c++) acc[r][c] = 0.f;

    const float* abase = attn + (b*SDIM + i0)*SDIM;
    for (int jc = 0; jc < SDIM; jc += 32) {
        #pragma unroll
        for (int e = 0; e < 8; e++) {
            int f = t + e*256; int row = f >> 5, col = f & 31;
            a_s[row][col] = abase[row*SDIM + jc + col];
        }
        #pragma unroll
        for (int e = 0; e < 16; e++) {
            int f = t + e*256; int kr = f >> 7, col = f & 127;
            v_s[kr][col] = g_v[(b*SDIM + jc + kr)*HDIM + col];
        }
        __syncthreads();
        #pragma unroll
        for (int kk = 0; kk < 32; kk++) {
            float4 b4 = *(const float4*)&v_s[kk][tx*4];
            #pragma unroll
            for (int r = 0; r < 8; r++) {
                float a = a_s[ty*8+r][kk];
                acc[r][0] += a*b4.x; acc[r][1] += a*b4.y;
                acc[r][2] += a*b4.z; acc[r][3] += a*b4.w;
            }
        }
        __syncthreads();
    }
    // rel_v contribution, K = 129 (zero-padded to 32-chunks)
    for (int pc = 0; pc < PDIM; pc += 32) {
        #pragma unroll
        for (int e = 0; e < 8; e++) {
            int f = t + e*256; int row = f >> 5, col = f & 31;
            int p = pc + col;
            a_s[row][col] = (p < PDIM) ? g_w[(b*SDIM + i0 + row)*PW + p] : 0.f;
        }
        #pragma unroll
        for (int e = 0; e < 16; e++) {
            int f = t + e*256; int kr = f >> 7, col = f & 127;
            int p = pc + kr;
            v_s[kr][col] = (p < PDIM) ? rel_v[p*HDIM + col] : 0.f;
        }
        __syncthreads();
        #pragma unroll
        for (int kk = 0; kk < 32; kk++) {
            float4 b4 = *(const float4*)&v_s[kk][tx*4];
            #pragma unroll
            for (int r = 0; r < 8; r++) {
                float a = a_s[ty*8+r][kk];
                acc[r][0] += a*b4.x; acc[r][1] += a*b4.y;
                acc[r][2] += a*b4.z; acc[r][3] += a*b4.w;
            }
        }
        __syncthreads();
    }
    #pragma unroll
    for (int r = 0; r < 8; r++) {
        float4 o = make_float4(acc[r][0], acc[r][1], acc[r][2], acc[r][3]);
        *(float4*)&g_ctx[(b*SDIM + i0 + ty*8 + r)*HDIM + tx*4] = o;
    }
}

// ============================================================================
// K4: out = ctx @ Wo + bo;  y = LayerNorm(out + x) * gamma + beta
// Tile 32 rows. GEMM then per-row two-pass LN via warp reductions.
// ============================================================================
__global__ __launch_bounds__(256) void k_out_ln(
    const float* __restrict__ x,
    const float* __restrict__ Wo, const float* __restrict__ bo,
    const float* __restrict__ gamma, const float* __restrict__ beta,
    float* __restrict__ y)
{
    __shared__ float Wos[32][128];
    __shared__ float cs[32][33];
    __shared__ float ys[32][128];
    int r0 = blockIdx.x * 32;
    int t  = threadIdx.x;
    int tx = t & 31, ty = t >> 5;

    float acc[4][4];
    #pragma unroll
    for (int r = 0; r < 4; r++)
        #pragma unroll
        for (int c = 0; c < 4; c++) acc[r][c] = 0.f;

    for (int kc = 0; kc < HDIM; kc += 32) {
        #pragma unroll
        for (int e = 0; e < 4; e++) {
            int f = t + e*256; int row = f >> 5, col = f & 31;
            cs[row][col] = g_ctx[(r0+row)*HDIM + kc + col];
        }
        #pragma unroll
        for (int e = 0; e < 16; e++) {
            int f = t + e*256; int kr = f >> 7, col = f & 127;
            Wos[kr][col] = Wo[(kc+kr)*HDIM + col];
        }
        __syncthreads();
        #pragma unroll
        for (int kk = 0; kk < 32; kk++) {
            float4 b4 = *(const float4*)&Wos[kk][tx*4];
            #pragma unroll
            for (int r = 0; r < 4; r++) {
                float a = cs[ty*4+r][kk];
                acc[r][0] += a*b4.x; acc[r][1] += a*b4.y;
                acc[r][2] += a*b4.z; acc[r][3] += a*b4.w;
            }
        }
        __syncthreads();
    }
    float4 bias = *(const float4*)&bo[tx*4];
    #pragma unroll
    for (int r = 0; r < 4; r++) {
        int row = ty*4 + r;
        float4 xr = *(const float4*)&x[(r0+row)*HDIM + tx*4];
        float4 o = make_float4(acc[r][0]+bias.x+xr.x, acc[r][1]+bias.y+xr.y,
                               acc[r][2]+bias.z+xr.z, acc[r][3]+bias.w+xr.w);
        *(float4*)&ys[row][tx*4] = o;
    }
    __syncthreads();

    int lane = t & 31, wz = t >> 5;
    #pragma unroll
    for (int r = 0; r < 4; r++) {
        int row = wz*4 + r;
        float s = 0.f;
        #pragma unroll
        for (int e = 0; e < 4; e++) s += ys[row][lane + 32*e];
        #pragma unroll
        for (int o = 16; o > 0; o >>= 1) s += __shfl_xor_sync(0xffffffffu, s, o);
        float mu = s * (1.f/128.f);
        float v = 0.f;
        #pragma unroll
        for (int e = 0; e < 4; e++) { float d = ys[row][lane+32*e] - mu; v += d*d; }
        #pragma unroll
        for (int o = 16; o > 0; o >>= 1) v += __shfl_xor_sync(0xffffffffu, v, o);
        float rstd = rsqrtf(v*(1.f/128.f) + LN_EPS);
        #pragma unroll
        for (int e = 0; e < 4; e++) {
            int c = lane + 32*e;
            y[(r0+row)*HDIM + c] = (ys[row][c] - mu)*rstd*gamma[c] + beta[c];
        }
    }
}

// ============================================================================
extern "C" void kernel_launch(void* const* d_in, const int* in_sizes, int n_in,
                              void* d_out, int out_size)
{
    const float* x     = (const float*)d_in[0];
    const float* Wq    = (const float*)d_in[1];
    const float* bq    = (const float*)d_in[2];
    const float* Wk    = (const float*)d_in[3];
    const float* bk    = (const float*)d_in[4];
    const float* Wv    = (const float*)d_in[5];
    const float* bv    = (const float*)d_in[6];
    const float* rel_k = (const float*)d_in[7];
    const float* rel_v = (const float*)d_in[8];
    const float* Wo    = (const float*)d_in[9];
    const float* bo    = (const float*)d_in[10];
    const float* gamma = (const float*)d_in[11];
    const float* beta  = (const float*)d_in[12];

    float* y = (float*)d_out;
    float* attn;
    if (out_size >= BDIM*SDIM*HDIM + BDIM*SDIM*SDIM) {
        attn = y + BDIM*SDIM*HDIM;          // reference returns (y, attn)
    } else {
        void* p = nullptr;
        cudaGetSymbolAddress(&p, g_attn);
        attn = (float*)p;
    }

    cudaFuncSetAttribute(k_scores, cudaFuncAttributeMaxDynamicSharedMemorySize,
                         SC_SMEM_BYTES);

    k_qkv   <<<dim3(BS/64, 3), 256>>>(x, Wq, bq, Wk, bk, Wv, bv);
    k_scores<<<dim3(SDIM/16, BDIM), 256, SC_SMEM_BYTES>>>(rel_k, attn);
    k_ctx   <<<dim3(SDIM/64, BDIM), 256>>>(attn, rel_v);
    k_out_ln<<<BS/32, 256>>>(x, Wo, bo, gamma, beta, y);
}